// round 17
// baseline (speedup 1.0000x reference)
#include <cuda_runtime.h>
#include <cuda_bf16.h>
#include <cuda_fp16.h>
#include <math.h>

#define NN 50000
#define NP 50048          // padded to 128
#define EE 800000
#define ET (EE + NN)      // edges + self loops
#define PIT 264           // smem row pitch (fp16): 33*16B -> LDSM conflict-free

// ---------------- scratch (device globals; no allocation allowed) ----------------
__device__ float d_T2[512 * 16];             // Hd @ Wr
__device__ float d_M[128 * 16];              // Wd @ T2
__device__ int   d_deg[NN];                  // starts 0; scan resets to 0 after use
__device__ int   d_rowoff[NN + 1];
__device__ int   d_cursor[NN];               // gcn_agg resets to 0 after scatter
__device__ float d_dis[NN];
__device__ int   d_csr[ET];
__device__ float d_xw[NN * 16];
__device__ float d_dual[NN * 16];
__device__ float d_h0[NN * 16];
__device__ __half d_h1h[NP * 256];           // fp16 transformed features (agg gather)
__device__ __half d_Ah[NP * 256];            // fp16 activations for layer-2 MMA (pads stay 0)
__device__ float d_bufA[NN * 256];
__device__ float d_sa[NN * 16];
__device__ float d_da[NN * 16];
__device__ __half d_W2h[256 * 256];          // W2^T [n][k] fp16
__device__ __half d_W3h[256 * 256];
__device__ int   d_mark[NN];                 // zero-init; compact resets to 0
__device__ int   d_list[NN];
__device__ int   d_listcnt;

// ================= chain A: degree count (8 edges/thread) =================
__global__ void k_count(const int* __restrict__ dst) {
    int t = blockIdx.x * blockDim.x + threadIdx.x;
    int e0 = t * 8;
    if (e0 + 7 < EE) {
        int4 a = *(const int4*)(dst + e0);
        int4 b = *(const int4*)(dst + e0 + 4);
        atomicAdd(&d_deg[a.x], 1);
        atomicAdd(&d_deg[a.y], 1);
        atomicAdd(&d_deg[a.z], 1);
        atomicAdd(&d_deg[a.w], 1);
        atomicAdd(&d_deg[b.x], 1);
        atomicAdd(&d_deg[b.y], 1);
        atomicAdd(&d_deg[b.z], 1);
        atomicAdd(&d_deg[b.w], 1);
    } else {
        for (int e = e0; e < EE; e++) atomicAdd(&d_deg[dst[e]], 1);
    }
}

// ================= chain B: prepW | gemmA =================
#define QB_PREPW 512
#define QB_GEMMA 1024
#define QB_TOTAL (QB_PREPW + QB_GEMMA)

__global__ void k_prep(const float* __restrict__ W2, const float* __restrict__ W3,
                       const float* __restrict__ hd, const float* __restrict__ wr) {
    int bid = blockIdx.x, tid = threadIdx.x;
    if (bid < QB_PREPW) {
        int idx = bid * 256 + tid;
        int sel = idx >> 16;
        int r = idx & 65535;
        int n = r >> 8, k = r & 255;
        float w = (sel ? W3 : W2)[k * 256 + n];
        __half h = __float2half_rn(w);
        if (sel) d_W3h[r] = h;
        else     d_W2h[r] = h;
    } else {
        int w = ((bid - QB_PREPW) * 256 + tid) >> 5;
        int lane = tid & 31;
        int i = w >> 4, j = w & 15;
        float a = 0.f;
#pragma unroll
        for (int kk = 0; kk < 16; kk++) {
            int k = lane + kk * 32;
            a += hd[i * 512 + k] * wr[k * 16 + j];
        }
#pragma unroll
        for (int off = 16; off >= 1; off >>= 1)
            a += __shfl_down_sync(0xffffffffu, a, off);
        if (lane == 0) d_T2[w] = a;
    }
}

// ================= chain A: scan (+ fused rsqrt degree, deg reset) =================
__global__ void __launch_bounds__(1024)
k_scan() {
    __shared__ int warp_sums[32];
    int t = threadIdx.x;
    const int S = 49;
    int b0 = t * S;
    int sum = 0;
    for (int i = 0; i < S; i++) {
        int idx = b0 + i;
        if (idx < NN) sum += d_deg[idx] + 1;
    }
    int lane = t & 31, w = t >> 5;
    int v = sum;
#pragma unroll
    for (int off = 1; off < 32; off <<= 1) {
        int u = __shfl_up_sync(0xffffffffu, v, off);
        if (lane >= off) v += u;
    }
    if (lane == 31) warp_sums[w] = v;
    __syncthreads();
    if (w == 0) {
        int ws = warp_sums[lane];
#pragma unroll
        for (int off = 1; off < 32; off <<= 1) {
            int u = __shfl_up_sync(0xffffffffu, ws, off);
            if (lane >= off) ws += u;
        }
        warp_sums[lane] = ws;
    }
    __syncthreads();
    int ex = v - sum + (w > 0 ? warp_sums[w - 1] : 0);
    int run = ex;
    for (int i = 0; i < S; i++) {
        int idx = b0 + i;
        if (idx < NN) {
            int dg = d_deg[idx] + 1;
            d_deg[idx] = 0;
            run += dg;
            d_rowoff[idx + 1] = run;
            d_dis[idx] = rsqrtf((float)dg);
        }
    }
    if (t == 0) d_rowoff[0] = 0;
}

// ================= chain B: gemmB =================
__global__ void __launch_bounds__(1024)
k_gemmB(const float* __restrict__ wd) {
    int w = blockIdx.x * 32 + (threadIdx.x >> 5);
    int lane = threadIdx.x & 31;
    int i = w >> 4, j = w & 15;
    float a = 0.f;
#pragma unroll
    for (int kk = 0; kk < 16; kk++) {
        int k = lane + kk * 32;
        a += wd[i * 512 + k] * d_T2[k * 16 + j];
    }
#pragma unroll
    for (int off = 16; off >= 1; off >>= 1)
        a += __shfl_down_sync(0xffffffffu, a, off);
    if (lane == 0) d_M[w] = a;
}

// ================= chain A: scatter =================
__global__ void k_scatter(const int* __restrict__ ei) {
    int e = blockIdx.x * blockDim.x + threadIdx.x;
    if (e >= ET) return;
    int s, dd;
    if (e < EE) { s = ei[e]; dd = ei[EE + e]; }
    else        { s = dd = e - EE; }
    int p = atomicAdd(&d_cursor[dd], 1);
    d_csr[d_rowoff[dd] + p] = s;
}

// ================= chain B: xw_dual (smem staged) =================
__global__ void __launch_bounds__(256)
k_xw_dual(const float* __restrict__ x, const float* __restrict__ Wg) {
    __shared__ float sx[16][132];
    int tid = threadIdx.x;
    int nb = blockIdx.x * 16;
    const float4* xs = (const float4*)(x + (size_t)nb * 128);
    for (int i = tid; i < 512; i += 256) {
        float4 v = xs[i];
        int r = i >> 5, c = (i & 31) * 4;
        sx[r][c] = v.x; sx[r][c + 1] = v.y; sx[r][c + 2] = v.z; sx[r][c + 3] = v.w;
    }
    __syncthreads();
    int nl = tid >> 4, j = tid & 15;
    float a = 0.f, b = 0.f;
#pragma unroll 4
    for (int k = 0; k < 128; k++) {
        float xv = sx[nl][k];
        a += xv * Wg[k * 16 + j];
        b += xv * d_M[k * 16 + j];
    }
    int n = nb + nl;
    d_xw[n * 16 + j] = a;
    d_dual[n * 16 + j] = b;
}

// ======= merged: GCN aggregation (float4 channels, 4-edge unroll) | mark set =======
#define GB_GCN ((NN * 4 + 255) / 256)

__global__ void k_gcn_agg(const float* __restrict__ bg,
                          const int* __restrict__ ui, const int* __restrict__ ii,
                          int P) {
    int bid = blockIdx.x, tid = threadIdx.x;
    if (bid < GB_GCN) {
        int t = bid * 256 + tid;
        int g = t >> 2, c4 = t & 3;
        if (g >= NN) return;
        int beg = d_rowoff[g], end = d_rowoff[g + 1];
        float4 acc = make_float4(0.f, 0.f, 0.f, 0.f);
        int e = beg;
        for (; e + 3 < end; e += 4) {
            int s0 = d_csr[e], s1 = d_csr[e + 1], s2 = d_csr[e + 2], s3 = d_csr[e + 3];
            float ds0 = d_dis[s0], ds1 = d_dis[s1], ds2 = d_dis[s2], ds3 = d_dis[s3];
            float4 x0 = ((const float4*)(d_xw + s0 * 16))[c4];
            float4 x1 = ((const float4*)(d_xw + s1 * 16))[c4];
            float4 x2 = ((const float4*)(d_xw + s2 * 16))[c4];
            float4 x3 = ((const float4*)(d_xw + s3 * 16))[c4];
            acc.x += ds0 * x0.x + ds1 * x1.x + ds2 * x2.x + ds3 * x3.x;
            acc.y += ds0 * x0.y + ds1 * x1.y + ds2 * x2.y + ds3 * x3.y;
            acc.z += ds0 * x0.z + ds1 * x1.z + ds2 * x2.z + ds3 * x3.z;
            acc.w += ds0 * x0.w + ds1 * x1.w + ds2 * x2.w + ds3 * x3.w;
        }
        for (; e < end; e++) {
            int s = d_csr[e];
            float ds = d_dis[s];
            float4 xw = ((const float4*)(d_xw + s * 16))[c4];
            acc.x += ds * xw.x; acc.y += ds * xw.y;
            acc.z += ds * xw.z; acc.w += ds * xw.w;
        }
        float dg = d_dis[g];
        float4 du = ((const float4*)(d_dual + g * 16))[c4];
        float4 vo;
        vo.x = acc.x * dg + bg[c4 * 4 + 0] + du.x;
        vo.y = acc.y * dg + bg[c4 * 4 + 1] + du.y;
        vo.z = acc.z * dg + bg[c4 * 4 + 2] + du.z;
        vo.w = acc.w * dg + bg[c4 * 4 + 3] + du.w;
        vo.x = vo.x > 0.f ? vo.x : (__expf(vo.x) - 1.f);
        vo.y = vo.y > 0.f ? vo.y : (__expf(vo.y) - 1.f);
        vo.z = vo.z > 0.f ? vo.z : (__expf(vo.z) - 1.f);
        vo.w = vo.w > 0.f ? vo.w : (__expf(vo.w) - 1.f);
        ((float4*)(d_h0 + g * 16))[c4] = vo;
        if (c4 == 0) d_cursor[g] = 0;   // reset for next replay
    } else {
        int i = (bid - GB_GCN) * 256 + tid;
        if (i == 0) d_listcnt = 0;
        if (i < 2 * P) {
            int n = (i < P) ? ui[i] : ii[i - P];
            d_mark[n] = 1;
            int beg = d_rowoff[n], end = d_rowoff[n + 1];
            for (int e = beg; e < end; e++) d_mark[d_csr[e]] = 1;
        }
    }
}

// ---------------- GAT layer-1 transform (FIN=16, FFMA; writes fp16 h1) ----------------
__global__ void __launch_bounds__(128, 8)
k_transform16(const float* __restrict__ hin, const float* __restrict__ W,
              const float* __restrict__ asrc, const float* __restrict__ adst) {
    __shared__ float s[16][16];
    int tid = threadIdx.x;
    int nb = blockIdx.x * 16;
    const float4* hin4 = (const float4*)(hin + nb * 16);
    float4* s4 = (float4*)s;
    for (int t = tid; t < 16 * 16 / 4; t += 128) s4[t] = hin4[t];
    __syncthreads();

    int cg = tid & 63;
    int ng = tid >> 6;
    const float4* W4 = (const float4*)W;
    float4 acc[8];
#pragma unroll
    for (int r = 0; r < 8; r++) acc[r] = make_float4(0.f, 0.f, 0.f, 0.f);

#pragma unroll
    for (int k = 0; k < 16; k++) {
        float4 w = W4[k * 64 + cg];
#pragma unroll
        for (int r = 0; r < 8; r++) {
            float sv = s[ng * 8 + r][k];
            acc[r].x += sv * w.x; acc[r].y += sv * w.y;
            acc[r].z += sv * w.z; acc[r].w += sv * w.w;
        }
    }

    float4 as4 = ((const float4*)asrc)[cg];
    float4 ad4 = ((const float4*)adst)[cg];
#pragma unroll
    for (int r = 0; r < 8; r++) {
        int n = nb + ng * 8 + r;
        if (n >= NN) break;
        __half2 p0 = __floats2half2_rn(acc[r].x, acc[r].y);
        __half2 p1 = __floats2half2_rn(acc[r].z, acc[r].w);
        *(__half2*)&d_h1h[(size_t)n * 256 + cg * 4] = p0;
        *(__half2*)&d_h1h[(size_t)n * 256 + cg * 4 + 2] = p1;
        float vs = acc[r].x * as4.x + acc[r].y * as4.y + acc[r].z * as4.z + acc[r].w * as4.w;
        float vd = acc[r].x * ad4.x + acc[r].y * ad4.y + acc[r].z * ad4.z + acc[r].w * ad4.w;
        vs += __shfl_down_sync(0xffffffffu, vs, 2, 4);
        vs += __shfl_down_sync(0xffffffffu, vs, 1, 4);
        vd += __shfl_down_sync(0xffffffffu, vd, 2, 4);
        vd += __shfl_down_sync(0xffffffffu, vd, 1, 4);
        if ((cg & 3) == 0) {
            int h = cg >> 2;
            d_sa[n * 16 + h] = vs;
            d_da[n * 16 + h] = vd;
        }
    }
}

// ---------------- MMA helpers ----------------
#define MMA_F16(C, A0, A1, A2, A3, B0, B1)                                   \
    asm volatile(                                                            \
        "mma.sync.aligned.m16n8k16.row.col.f32.f16.f16.f32 "                 \
        "{%0,%1,%2,%3}, {%4,%5,%6,%7}, {%8,%9}, {%0,%1,%2,%3};\n"            \
        : "+f"(C[0]), "+f"(C[1]), "+f"(C[2]), "+f"(C[3])                     \
        : "r"(A0), "r"(A1), "r"(A2), "r"(A3), "r"(B0), "r"(B1))

#define LDSM4(R0, R1, R2, R3, ADDR)                                          \
    asm volatile("ldmatrix.sync.aligned.m8n8.x4.shared.b16 {%0,%1,%2,%3}, [%4];" \
        : "=r"(R0), "=r"(R1), "=r"(R2), "=r"(R3) : "r"(ADDR))

#define SMEM_MMA ((128 * PIT + 64 * PIT) * 2)

// mainloop + epilogue over one 64-col B slice; writes rows g0,g1 (-1 = skip)
static __device__ __forceinline__ void mma_core(__half* sA, __half* sB,
                                                int lane, int warp, int n0,
                                                const float* __restrict__ as_,
                                                const float* __restrict__ ad_,
                                                int g0, int g1) {
    float c[8][4];
#pragma unroll
    for (int t = 0; t < 8; t++)
#pragma unroll
        for (int j = 0; j < 4; j++) c[t][j] = 0.f;

    int rA = warp * 16 + (lane & 15);
    int kOff = (lane >> 4) << 3;
    unsigned aB = (unsigned)__cvta_generic_to_shared(sA + rA * PIT + kOff);
    int rB = lane & 15;
    unsigned bB = (unsigned)__cvta_generic_to_shared(sB + rB * PIT + kOff);

#pragma unroll 4
    for (int kc = 0; kc < 16; kc++) {
        unsigned ka = kc * 32;
        unsigned a0, a1, a2, a3;
        LDSM4(a0, a1, a2, a3, aB + ka);
#pragma unroll
        for (int p = 0; p < 4; p++) {
            unsigned boff = (unsigned)(p * 16 * PIT * 2) + ka;
            unsigned b0, b1, b2, b3;
            LDSM4(b0, b1, b2, b3, bB + boff);
            MMA_F16(c[2 * p],     a0, a1, a2, a3, b0, b2);
            MMA_F16(c[2 * p + 1], a0, a1, a2, a3, b1, b3);
        }
    }

    int H0 = n0 >> 4;
    int cbase = (lane & 3) * 2;
    float vs0[4] = {0, 0, 0, 0}, vd0[4] = {0, 0, 0, 0};
    float vs1[4] = {0, 0, 0, 0}, vd1[4] = {0, 0, 0, 0};
#pragma unroll
    for (int t = 0; t < 8; t++) {
        int col = n0 + t * 8 + cbase;
        if (g0 >= 0)
            *(__half2*)&d_h1h[(size_t)g0 * 256 + col] = __floats2half2_rn(c[t][0], c[t][1]);
        if (g1 >= 0)
            *(__half2*)&d_h1h[(size_t)g1 * 256 + col] = __floats2half2_rn(c[t][2], c[t][3]);
        float2 a2 = *(const float2*)&as_[col];
        float2 d2 = *(const float2*)&ad_[col];
        int hh = t >> 1;
        vs0[hh] += c[t][0] * a2.x + c[t][1] * a2.y;
        vd0[hh] += c[t][0] * d2.x + c[t][1] * d2.y;
        vs1[hh] += c[t][2] * a2.x + c[t][3] * a2.y;
        vd1[hh] += c[t][2] * d2.x + c[t][3] * d2.y;
    }
#pragma unroll
    for (int hh = 0; hh < 4; hh++) {
        vs0[hh] += __shfl_down_sync(0xffffffffu, vs0[hh], 2, 4);
        vs0[hh] += __shfl_down_sync(0xffffffffu, vs0[hh], 1, 4);
        vd0[hh] += __shfl_down_sync(0xffffffffu, vd0[hh], 2, 4);
        vd0[hh] += __shfl_down_sync(0xffffffffu, vd0[hh], 1, 4);
        vs1[hh] += __shfl_down_sync(0xffffffffu, vs1[hh], 2, 4);
        vs1[hh] += __shfl_down_sync(0xffffffffu, vs1[hh], 1, 4);
        vd1[hh] += __shfl_down_sync(0xffffffffu, vd1[hh], 2, 4);
        vd1[hh] += __shfl_down_sync(0xffffffffu, vd1[hh], 1, 4);
    }
    if ((lane & 3) == 0) {
        if (g0 >= 0 && g0 < NN) {
#pragma unroll
            for (int hh = 0; hh < 4; hh++) {
                d_sa[g0 * 16 + H0 + hh] = vs0[hh];
                d_da[g0 * 16 + H0 + hh] = vd0[hh];
            }
        }
        if (g1 >= 0 && g1 < NN) {
#pragma unroll
            for (int hh = 0; hh < 4; hh++) {
                d_sa[g1 * 16 + H0 + hh] = vs1[hh];
                d_da[g1 * 16 + H0 + hh] = vd1[hh];
            }
        }
    }
}

static __device__ __forceinline__ void stage_B(__half* sB, const __half* __restrict__ Bh,
                                               int n0, int tid) {
    const uint4* bH = (const uint4*)(Bh + (size_t)n0 * 256);
    for (int i = tid; i < 64 * 32; i += 256) {
        int r = i >> 5, c = i & 31;
        *(uint4*)(sB + r * PIT + c * 8) = bH[r * 32 + c];
    }
}

// layer-2: all rows; 2 sequential 64-col slices per block (A staged once)
__global__ void __launch_bounds__(256, 1)
k_transform_mma(const __half* __restrict__ Bh,
                const float* __restrict__ as_, const float* __restrict__ ad_) {
    extern __shared__ __half sm[];
    __half* sA = sm;
    __half* sB = sA + 128 * PIT;
    int tid = threadIdx.x, lane = tid & 31, warp = tid >> 5;
    int m0 = blockIdx.x * 128;
    {
        const uint4* gA = (const uint4*)(d_Ah + (size_t)m0 * 256);
        for (int i = tid; i < 128 * 32; i += 256) {
            int r = i >> 5, c = i & 31;
            *(uint4*)(sA + r * PIT + c * 8) = gA[r * 32 + c];
        }
    }
    int g0 = m0 + warp * 16 + (lane >> 2);
#pragma unroll
    for (int s = 0; s < 2; s++) {
        int n0 = blockIdx.y * 128 + s * 64;
        stage_B(sB, Bh, n0, tid);
        __syncthreads();
        mma_core(sA, sB, lane, warp, n0, as_, ad_, g0, g0 + 8);
        __syncthreads();
    }
}

// layer-3: only listed rows (gather A by index, scatter outputs)
__global__ void __launch_bounds__(256, 1)
k_transform_mma_idx(const __half* __restrict__ Bh,
                    const float* __restrict__ as_, const float* __restrict__ ad_) {
    extern __shared__ __half sm[];
    __shared__ int snode[128];
    __half* sA = sm;
    __half* sB = sA + 128 * PIT;
    int tid = threadIdx.x, lane = tid & 31, warp = tid >> 5;
    int m0 = blockIdx.x * 128;
    int cnt = d_listcnt;
    if (m0 >= cnt) return;
    for (int i = tid; i < 128; i += 256) {
        int r = m0 + i;
        snode[i] = (r < cnt) ? d_list[r] : -1;
    }
    __syncthreads();
    for (int i = tid; i < 128 * 32; i += 256) {
        int r = i >> 5, c = i & 31;
        int nd = snode[r];
        uint4 v = make_uint4(0, 0, 0, 0);
        if (nd >= 0) v = ((const uint4*)(d_Ah + (size_t)nd * 256))[c];
        *(uint4*)(sA + r * PIT + c * 8) = v;
    }
    int r0 = warp * 16 + (lane >> 2);
#pragma unroll
    for (int s = 0; s < 2; s++) {
        int n0 = blockIdx.y * 128 + s * 64;
        stage_B(sB, Bh, n0, tid);
        __syncthreads();
        mma_core(sA, sB, lane, warp, n0, as_, ad_, snode[r0], snode[r0 + 8]);
        __syncthreads();
    }
}

// ====== GAT aggregation body, head-split: warp w handles heads 8w..8w+7 ======
// lane owns 4 channels: ch = w*128 + lane*4 .. +4; head hd = w*8 + (lane>>2)
template <bool SPLIT>
static __device__ __forceinline__ void gat_body_hs(int n, int lane, int w,
                                                   const float* __restrict__ b,
                                                   float* __restrict__ outf) {
    int hd = w * 8 + (lane >> 2);
    int chb = w * 128 + lane * 4;
    float da_l = d_da[n * 16 + hd];
    int beg = d_rowoff[n], end = d_rowoff[n + 1];

    float m = -1e30f, z = 0.f;
    float acc[4] = {0.f, 0.f, 0.f, 0.f};

    int e = beg;
    for (; e + 3 < end; e += 4) {
        int s0 = d_csr[e], s1 = d_csr[e + 1], s2 = d_csr[e + 2], s3 = d_csr[e + 3];
        float l0 = d_sa[s0 * 16 + hd] + da_l;
        float l1 = d_sa[s1 * 16 + hd] + da_l;
        float l2 = d_sa[s2 * 16 + hd] + da_l;
        float l3 = d_sa[s3 * 16 + hd] + da_l;
        uint2 hv0 = *(const uint2*)(d_h1h + (size_t)s0 * 256 + chb);
        uint2 hv1 = *(const uint2*)(d_h1h + (size_t)s1 * 256 + chb);
        uint2 hv2 = *(const uint2*)(d_h1h + (size_t)s2 * 256 + chb);
        uint2 hv3 = *(const uint2*)(d_h1h + (size_t)s3 * 256 + chb);
        l0 = l0 > 0.f ? l0 : 0.2f * l0;
        l1 = l1 > 0.f ? l1 : 0.2f * l1;
        l2 = l2 > 0.f ? l2 : 0.2f * l2;
        l3 = l3 > 0.f ? l3 : 0.2f * l3;
        float nm = fmaxf(fmaxf(m, fmaxf(l0, l1)), fmaxf(l2, l3));
        float sc = __expf(m - nm);
        float e0 = __expf(l0 - nm), e1 = __expf(l1 - nm);
        float e2 = __expf(l2 - nm), e3 = __expf(l3 - nm);
        m = nm;
        z = z * sc + (e0 + e1) + (e2 + e3);
        float2 f0 = __half22float2(*(__half2*)&hv0.x), f1 = __half22float2(*(__half2*)&hv0.y);
        float2 g0 = __half22float2(*(__half2*)&hv1.x), g1 = __half22float2(*(__half2*)&hv1.y);
        float2 p0 = __half22float2(*(__half2*)&hv2.x), p1 = __half22float2(*(__half2*)&hv2.y);
        float2 q0 = __half22float2(*(__half2*)&hv3.x), q1 = __half22float2(*(__half2*)&hv3.y);
        acc[0] = acc[0] * sc + (e0 * f0.x + e1 * g0.x) + (e2 * p0.x + e3 * q0.x);
        acc[1] = acc[1] * sc + (e0 * f0.y + e1 * g0.y) + (e2 * p0.y + e3 * q0.y);
        acc[2] = acc[2] * sc + (e0 * f1.x + e1 * g1.x) + (e2 * p1.x + e3 * q1.x);
        acc[3] = acc[3] * sc + (e0 * f1.y + e1 * g1.y) + (e2 * p1.y + e3 * q1.y);
    }
    for (; e < end; e++) {
        int s0 = d_csr[e];
        float l0 = d_sa[s0 * 16 + hd] + da_l;
        uint2 hv0 = *(const uint2*)(d_h1h + (size_t)s0 * 256 + chb);
        l0 = l0 > 0.f ? l0 : 0.2f * l0;
        float nm = fmaxf(m, l0);
        float sc = __expf(m - nm);
        float e0 = __expf(l0 - nm);
        m = nm;
        z = z * sc + e0;
        float2 f0 = __half22float2(*(__half2*)&hv0.x), f1 = __half22float2(*(__half2*)&hv0.y);
        acc[0] = acc[0] * sc + e0 * f0.x;
        acc[1] = acc[1] * sc + e0 * f0.y;
        acc[2] = acc[2] * sc + e0 * f1.x;
        acc[3] = acc[3] * sc + e0 * f1.y;
    }

    float invz = 1.f / (z + 1e-16f);
    float vo[4];
#pragma unroll
    for (int i = 0; i < 4; i++) {
        float v = acc[i] * invz + b[chb + i];
        vo[i] = v > 0.f ? v : (__expf(v) - 1.f);
    }
    if (SPLIT) {
        __half2 h0 = __floats2half2_rn(vo[0], vo[1]);
        __half2 h1 = __floats2half2_rn(vo[2], vo[3]);
        uint2 pk;
        pk.x = *(unsigned*)&h0; pk.y = *(unsigned*)&h1;
        *(uint2*)&d_Ah[(size_t)n * 256 + chb] = pk;
    } else {
        *(float4*)&outf[(size_t)n * 256 + chb] = make_float4(vo[0], vo[1], vo[2], vo[3]);
    }
}

// layer-1 agg (all nodes, 2 warps/node) | compact tail blocks
#define AB_AGG ((NN * 64) / 256)
#define AB_CMP ((NN + 255) / 256)

__global__ void k_agg1(const float* __restrict__ b) {
    int bid = blockIdx.x;
    if (bid < AB_AGG) {
        int gw = (bid * 256 + threadIdx.x) >> 5;   // global warp
        int n = gw >> 1, w = gw & 1;
        if (n >= NN) return;
        gat_body_hs<true>(n, threadIdx.x & 31, w, b, nullptr);
    } else {
        int i = (bid - AB_AGG) * 256 + threadIdx.x;
        if (i < NN && d_mark[i]) {
            int pos = atomicAdd(&d_listcnt, 1);
            d_list[pos] = i;
            d_mark[i] = 0;
        }
    }
}

// layer-2 agg: only listed nodes (2 warps/node)
__global__ void k_agg2_idx(const float* __restrict__ b) {
    int gw = (blockIdx.x * blockDim.x + threadIdx.x) >> 5;
    int i = gw >> 1, w = gw & 1;
    if (i >= d_listcnt) return;
    gat_body_hs<true>(d_list[i], threadIdx.x & 31, w, b, nullptr);
}

// layer-3: aggregate ONLY the user/item nodes (2 warps/node)
__global__ void k_gat_agg_list(const float* __restrict__ b, float* __restrict__ outf,
                               const int* __restrict__ ui, const int* __restrict__ ii,
                               int P) {
    int gw = (blockIdx.x * blockDim.x + threadIdx.x) >> 5;
    int i = gw >> 1, w = gw & 1;
    if (i >= 2 * P) return;
    int n = (i < P) ? ui[i] : ii[i - P];
    gat_body_hs<false>(n, threadIdx.x & 31, w, b, outf);
}

// ---------------- final ----------------
__global__ void k_final(const float* __restrict__ h, const int* __restrict__ ui,
                        const int* __restrict__ ii, const float* __restrict__ Wd,
                        float* __restrict__ out) {
    int p = (blockIdx.x * blockDim.x + threadIdx.x) >> 5;
    if (p >= 1024) return;
    int lane = threadIdx.x & 31;
    int u = ui[p], it = ii[p];
    float a0 = 0.f, a1 = 0.f;
    for (int k = lane; k < 256; k += 32) {
        float v = h[u * 256 + k];
        a0 += v * Wd[k * 2 + 0];
        a1 += v * Wd[k * 2 + 1];
        float w = h[it * 256 + k];
        a0 += w * Wd[(256 + k) * 2 + 0];
        a1 += w * Wd[(256 + k) * 2 + 1];
    }
#pragma unroll
    for (int off = 16; off >= 1; off >>= 1) {
        a0 += __shfl_down_sync(0xffffffffu, a0, off);
        a1 += __shfl_down_sync(0xffffffffu, a1, off);
    }
    if (lane == 0) {
        float mx = fmaxf(a0, a1);
        float lse = mx + __logf(__expf(a0 - mx) + __expf(a1 - mx));
        out[p * 2 + 0] = a0 - lse;
        out[p * 2 + 1] = a1 - lse;
    }
}

// ---------------- launcher ----------------
extern "C" void kernel_launch(void* const* d_in, const int* in_sizes, int n_in,
                              void* d_out, int out_size) {
    const float* x    = (const float*)d_in[0];
    const int*   ei   = (const int*)d_in[1];
    const float* Hd   = (const float*)d_in[2];
    const int*   ui   = (const int*)d_in[3];
    const int*   ii   = (const int*)d_in[4];
    const float* Wg   = (const float*)d_in[5];
    const float* bg   = (const float*)d_in[6];
    const float* W1   = (const float*)d_in[7];
    const float* a1s  = (const float*)d_in[8];
    const float* a1d  = (const float*)d_in[9];
    const float* b1   = (const float*)d_in[10];
    const float* W2   = (const float*)d_in[11];
    const float* a2s  = (const float*)d_in[12];
    const float* a2d  = (const float*)d_in[13];
    const float* b2   = (const float*)d_in[14];
    const float* W3   = (const float*)d_in[15];
    const float* a3s  = (const float*)d_in[16];
    const float* a3d  = (const float*)d_in[17];
    const float* b3   = (const float*)d_in[18];
    const float* wd   = (const float*)d_in[19];
    const float* wr   = (const float*)d_in[20];
    const float* wdnn = (const float*)d_in[21];
    float* out = (float*)d_out;

    int P = in_sizes[3];   // number of user/item pairs

    void *p_h0, *p_bufA, *p_w2h, *p_w3h;
    cudaGetSymbolAddress(&p_h0, d_h0);
    cudaGetSymbolAddress(&p_bufA, d_bufA);
    cudaGetSymbolAddress(&p_w2h, d_W2h);
    cudaGetSymbolAddress(&p_w3h, d_W3h);
    float* h0   = (float*)p_h0;
    float* bufA = (float*)p_bufA;

    cudaFuncSetAttribute(k_transform_mma,
                         cudaFuncAttributeMaxDynamicSharedMemorySize, SMEM_MMA);
    cudaFuncSetAttribute(k_transform_mma_idx,
                         cudaFuncAttributeMaxDynamicSharedMemorySize, SMEM_MMA);

    // fork: chain B (dense prep) on sB, chain A (graph build) on the default stream
    cudaStream_t sB;
    cudaStreamCreateWithFlags(&sB, cudaStreamNonBlocking);
    cudaEvent_t evFork, evJoin;
    cudaEventCreateWithFlags(&evFork, cudaEventDisableTiming);
    cudaEventCreateWithFlags(&evJoin, cudaEventDisableTiming);

    cudaEventRecord(evFork, 0);
    cudaStreamWaitEvent(sB, evFork, 0);

    // chain B: prepW | gemmA -> gemmB -> xw_dual
    k_prep<<<QB_TOTAL, 256, 0, sB>>>(W2, W3, Hd, wr);
    k_gemmB<<<64, 1024, 0, sB>>>(wd);
    k_xw_dual<<<NN / 16, 256, 0, sB>>>(x, Wg);
    cudaEventRecord(evJoin, sB);

    // chain A: count -> scan -> scatter
    k_count<<<(EE / 8 + 255) / 256, 256>>>(ei + EE);
    k_scan<<<1, 1024>>>();
    k_scatter<<<(ET + 255) / 256, 256>>>(ei);

    // join
    cudaStreamWaitEvent(0, evJoin, 0);

    k_gcn_agg<<<GB_GCN + (2 * P + 255) / 256, 256>>>(bg, ui, ii, P);

    // GAT layer 1 (all nodes) + compact tail
    k_transform16<<<NN / 16, 128>>>(h0, W1, a1s, a1d);
    k_agg1<<<AB_AGG + AB_CMP, 256>>>(b1);

    // GAT layer 2: transform all nodes (A staged once per block, 2 B slices)
    k_transform_mma<<<dim3(NP / 128, 2), 256, SMEM_MMA>>>(
        (const __half*)p_w2h, a2s, a2d);
    k_agg2_idx<<<AB_AGG, 256>>>(b2);

    // GAT layer 3: transform only marked set (indexed), aggregate only listed nodes
    k_transform_mma_idx<<<dim3(NP / 128, 2), 256, SMEM_MMA>>>(
        (const __half*)p_w3h, a3s, a3d);
    k_gat_agg_list<<<(2 * P * 64 + 255) / 256, 256>>>(b3, bufA, ui, ii, P);

    k_final<<<(1024 * 32 + 255) / 256, 256>>>(bufA, ui, ii, wdnn, out);

    cudaEventDestroy(evFork);
    cudaEventDestroy(evJoin);
    cudaStreamDestroy(sB);
}